// round 2
// baseline (speedup 1.0000x reference)
#include <cuda_runtime.h>
#include <math.h>

#define D_    768
#define H_    12
#define HD_   64
#define DFF_  3072
#define MAXT  8192
#define SMAX_ 1024

// ---------------- scratch (no allocations allowed) ----------------
__device__ float g_xn  [(size_t)MAXT * D_];      // LN output (reused for LN1 and LN2)
__device__ float g_qkv [(size_t)MAXT * 3 * D_];  // qkv projection
__device__ float g_attn[(size_t)MAXT * D_];      // attention output
__device__ float g_x2  [(size_t)MAXT * D_];      // residual after attention
__device__ float g_mid [(size_t)MAXT * DFF_];    // FFN hidden

// ---------------- LayerNorm: one block per token ----------------
__global__ void __launch_bounds__(256) ln_kernel(const float* __restrict__ x,
                                                 const float* __restrict__ g,
                                                 const float* __restrict__ be,
                                                 float* __restrict__ y) {
    int t = blockIdx.x;
    const float* xr = x + (size_t)t * D_;
    float*       yr = y + (size_t)t * D_;
    int tid = threadIdx.x;
    float v0 = xr[tid], v1 = xr[tid + 256], v2 = xr[tid + 512];
    float s  = v0 + v1 + v2;
    float s2 = v0 * v0 + v1 * v1 + v2 * v2;
    __shared__ float sh1[256], sh2[256];
    sh1[tid] = s; sh2[tid] = s2;
    __syncthreads();
    for (int o = 128; o > 0; o >>= 1) {
        if (tid < o) { sh1[tid] += sh1[tid + o]; sh2[tid] += sh2[tid + o]; }
        __syncthreads();
    }
    float mu  = sh1[0] * (1.0f / D_);
    float var = sh2[0] * (1.0f / D_) - mu * mu;
    float r   = rsqrtf(var + 1e-6f);
    yr[tid]       = (v0 - mu) * r * g[tid]       + be[tid];
    yr[tid + 256] = (v1 - mu) * r * g[tid + 256] + be[tid + 256];
    yr[tid + 512] = (v2 - mu) * r * g[tid + 512] + be[tid + 512];
}

// ---------------- Tiled SGEMM 128x128x8, 256 threads, 8x8 microtile ----------------
// EPI: 0 = +bias, 1 = +bias+residual, 2 = +bias then exact GELU
template <int EPI>
__global__ void __launch_bounds__(256) gemm_k(const float* __restrict__ A,
                                              const float* __restrict__ B,
                                              const float* __restrict__ bias,
                                              const float* __restrict__ res,
                                              float* __restrict__ C,
                                              int M, int N, int K) {
    __shared__ float As[8][128];
    __shared__ float Bs[8][128];
    int tid = threadIdx.x;
    int bm = blockIdx.y * 128, bn = blockIdx.x * 128;

    int aRow = tid >> 1;            // 0..127
    int aCol = (tid & 1) * 4;       // 0 or 4
    int bRow = tid >> 5;            // 0..7
    int bCol = (tid & 31) * 4;      // 0..124
    const float* Ag = A + (size_t)(bm + aRow) * K + aCol;
    const float* Bg = B + (size_t)bRow * N + bn + bCol;

    int tr = tid >> 4, tc = tid & 15;
    float acc[8][8];
#pragma unroll
    for (int i = 0; i < 8; i++)
#pragma unroll
        for (int j = 0; j < 8; j++) acc[i][j] = 0.f;

    for (int k0 = 0; k0 < K; k0 += 8) {
        float4 av = *(const float4*)(Ag + k0);
        float4 bv = *(const float4*)(Bg + (size_t)k0 * N);
        As[aCol + 0][aRow] = av.x;
        As[aCol + 1][aRow] = av.y;
        As[aCol + 2][aRow] = av.z;
        As[aCol + 3][aRow] = av.w;
        *(float4*)&Bs[bRow][bCol] = bv;
        __syncthreads();
#pragma unroll
        for (int k = 0; k < 8; k++) {
            float ar[8], br[8];
            *(float4*)(ar)     = *(const float4*)&As[k][tr * 8];
            *(float4*)(ar + 4) = *(const float4*)&As[k][tr * 8 + 4];
            *(float4*)(br)     = *(const float4*)&Bs[k][tc * 8];
            *(float4*)(br + 4) = *(const float4*)&Bs[k][tc * 8 + 4];
#pragma unroll
            for (int i = 0; i < 8; i++)
#pragma unroll
                for (int j = 0; j < 8; j++) acc[i][j] += ar[i] * br[j];
        }
        __syncthreads();
    }

#pragma unroll
    for (int i = 0; i < 8; i++) {
        int row = bm + tr * 8 + i;
        float out[8];
#pragma unroll
        for (int j = 0; j < 8; j++) {
            int col = bn + tc * 8 + j;
            float v = acc[i][j] + bias[col];
            if (EPI == 1) v += res[(size_t)row * N + col];
            if (EPI == 2) v = 0.5f * v * (1.0f + erff(v * 0.70710678118f));
            out[j] = v;
        }
        float* cp = C + (size_t)row * N + bn + tc * 8;
        *(float4*)(cp)     = *(float4*)(out);
        *(float4*)(cp + 4) = *(float4*)(out + 4);
    }
}

// ---------------- Ragged flash attention ----------------
// grid: (S_MAX/32 q-tiles, H, B). block: 256 threads.
// Thread layout: qg = tid>>4 (owns queries 2*qg, 2*qg+1), kx = tid&15.
// Per 64-key tile: thread computes scores for keys kx*4..kx*4+3, writes exp'd
// probs to Ps, then accumulates output dims kx*4..kx*4+3 over ALL 64 keys.
__global__ void __launch_bounds__(256) attn_kernel(const float* __restrict__ qkv,
                                                   const int* __restrict__ cu,
                                                   float* __restrict__ out) {
    int qt = blockIdx.x, h = blockIdx.y, b = blockIdx.z;
    int base = cu[b];
    int len  = cu[b + 1] - base;
    int q0   = qt * 32;
    if (q0 >= len) return;
    int nq = min(32, len - q0);

    __shared__ float Qs[32][68];
    __shared__ float KsT[64][68];   // K transposed: KsT[d][j]
    __shared__ float Vs[64][68];
    __shared__ float Ps[32][68];    // probabilities: Ps[q][j]

    int tid = threadIdx.x;
    // load Q tile (scaled)
    for (int idx = tid; idx < 32 * 64; idx += 256) {
        int qi = idx >> 6, d = idx & 63;
        Qs[qi][d] = (qi < nq)
            ? qkv[(size_t)(base + q0 + qi) * 2304 + h * 64 + d] * 0.125f
            : 0.f;
    }

    int qg = tid >> 4;
    int kx = tid & 15;
    int qa = qg * 2, qb = qg * 2 + 1;

    float m0 = -1e30f, m1 = -1e30f, l0 = 0.f, l1 = 0.f;
    float o0[4] = {0.f, 0.f, 0.f, 0.f}, o1[4] = {0.f, 0.f, 0.f, 0.f};

    for (int k0 = 0; k0 < len; k0 += 64) {
        int nk = min(64, len - k0);
        __syncthreads();   // Q visible (iter 0) / prev-iter consumers done
        for (int idx = tid; idx < 64 * 64; idx += 256) {
            int j = idx >> 6, d = idx & 63;
            float kv = 0.f, vv = 0.f;
            if (j < nk) {
                size_t r = (size_t)(base + k0 + j) * 2304 + h * 64 + d;
                kv = qkv[r + 768];
                vv = qkv[r + 1536];
            }
            KsT[d][j] = kv;
            Vs[j][d]  = vv;
        }
        __syncthreads();

        // scores: 2 queries x 4 keys per thread
        float s[2][4];
#pragma unroll
        for (int c = 0; c < 4; c++) { s[0][c] = 0.f; s[1][c] = 0.f; }
#pragma unroll
        for (int d = 0; d < 64; d++) {
            float qv0 = Qs[qa][d];
            float qv1 = Qs[qb][d];
            float4 kq = *(const float4*)&KsT[d][kx * 4];
            s[0][0] += qv0 * kq.x; s[0][1] += qv0 * kq.y;
            s[0][2] += qv0 * kq.z; s[0][3] += qv0 * kq.w;
            s[1][0] += qv1 * kq.x; s[1][1] += qv1 * kq.y;
            s[1][2] += qv1 * kq.z; s[1][3] += qv1 * kq.w;
        }
#pragma unroll
        for (int c = 0; c < 4; c++) {
            if (kx * 4 + c >= nk) { s[0][c] = -1e30f; s[1][c] = -1e30f; }
        }

        // row max across the 16 kx threads (lanes (qg&1)*16 + kx in the warp)
        float tm0 = fmaxf(fmaxf(s[0][0], s[0][1]), fmaxf(s[0][2], s[0][3]));
        float tm1 = fmaxf(fmaxf(s[1][0], s[1][1]), fmaxf(s[1][2], s[1][3]));
#pragma unroll
        for (int off = 8; off >= 1; off >>= 1) {
            tm0 = fmaxf(tm0, __shfl_xor_sync(0xffffffffu, tm0, off));
            tm1 = fmaxf(tm1, __shfl_xor_sync(0xffffffffu, tm1, off));
        }
        float nm0 = fmaxf(m0, tm0), nm1 = fmaxf(m1, tm1);
        float sc0 = __expf(m0 - nm0), sc1 = __expf(m1 - nm1);

        float p0[4], p1[4];
        float ls0 = 0.f, ls1 = 0.f;
#pragma unroll
        for (int c = 0; c < 4; c++) {
            p0[c] = __expf(s[0][c] - nm0);
            p1[c] = __expf(s[1][c] - nm1);
            ls0 += p0[c]; ls1 += p1[c];
        }
        // publish probabilities for the full PV accumulation
        *(float4*)&Ps[qa][kx * 4] = *(float4*)p0;
        *(float4*)&Ps[qb][kx * 4] = *(float4*)p1;
#pragma unroll
        for (int off = 8; off >= 1; off >>= 1) {
            ls0 += __shfl_xor_sync(0xffffffffu, ls0, off);
            ls1 += __shfl_xor_sync(0xffffffffu, ls1, off);
        }
        l0 = l0 * sc0 + ls0;
        l1 = l1 * sc1 + ls1;
        m0 = nm0; m1 = nm1;

#pragma unroll
        for (int dd = 0; dd < 4; dd++) { o0[dd] *= sc0; o1[dd] *= sc1; }

        __syncthreads();   // Ps visible to all threads

        // PV: accumulate output dims kx*4..kx*4+3 over ALL keys of the tile
#pragma unroll 8
        for (int j = 0; j < 64; j++) {
            float pj0 = Ps[qa][j];
            float pj1 = Ps[qb][j];
            float4 vv = *(const float4*)&Vs[j][kx * 4];
            o0[0] += pj0 * vv.x; o0[1] += pj0 * vv.y;
            o0[2] += pj0 * vv.z; o0[3] += pj0 * vv.w;
            o1[0] += pj1 * vv.x; o1[1] += pj1 * vv.y;
            o1[2] += pj1 * vv.z; o1[3] += pj1 * vv.w;
        }
    }

    float inv0 = 1.0f / l0, inv1 = 1.0f / l1;
    if (qa < nq) {
        float w[4];
#pragma unroll
        for (int dd = 0; dd < 4; dd++) w[dd] = o0[dd] * inv0;
        *(float4*)&out[(size_t)(base + q0 + qa) * D_ + h * 64 + kx * 4] = *(float4*)w;
    }
    if (qb < nq) {
        float w[4];
#pragma unroll
        for (int dd = 0; dd < 4; dd++) w[dd] = o1[dd] * inv1;
        *(float4*)&out[(size_t)(base + q0 + qb) * D_ + h * 64 + kx * 4] = *(float4*)w;
    }
}

// ---------------- host launch ----------------
extern "C" void kernel_launch(void* const* d_in, const int* in_sizes, int n_in,
                              void* d_out, int out_size) {
    const float* x     = (const float*)d_in[0];
    const int*   cu    = (const int*)  d_in[1];
    const float* g1    = (const float*)d_in[2];
    const float* beta1 = (const float*)d_in[3];
    const float* Wqkv  = (const float*)d_in[4];
    const float* bqkv  = (const float*)d_in[5];
    const float* Wo    = (const float*)d_in[6];
    const float* bo    = (const float*)d_in[7];
    const float* g2    = (const float*)d_in[8];
    const float* beta2 = (const float*)d_in[9];
    const float* W1    = (const float*)d_in[10];
    const float* b_fc1 = (const float*)d_in[11];
    const float* W2    = (const float*)d_in[12];
    const float* b_fc2 = (const float*)d_in[13];
    float* out = (float*)d_out;

    int total = in_sizes[0] / D_;   // 6144 (multiple of 128)
    int nb    = in_sizes[1] - 1;    // 8

    float *xn, *qkv, *attn, *x2, *mid;
    cudaGetSymbolAddress((void**)&xn,   g_xn);
    cudaGetSymbolAddress((void**)&qkv,  g_qkv);
    cudaGetSymbolAddress((void**)&attn, g_attn);
    cudaGetSymbolAddress((void**)&x2,   g_x2);
    cudaGetSymbolAddress((void**)&mid,  g_mid);

    int mb = total / 128;

    // 1. LN1
    ln_kernel<<<total, 256>>>(x, g1, beta1, xn);
    // 2. QKV projection
    gemm_k<0><<<dim3(3 * D_ / 128, mb), 256>>>(xn, Wqkv, bqkv, nullptr, qkv,
                                               total, 3 * D_, D_);
    // 3. ragged attention
    attn_kernel<<<dim3(SMAX_ / 32, H_, nb), 256>>>(qkv, cu, attn);
    // 4. output projection + residual
    gemm_k<1><<<dim3(D_ / 128, mb), 256>>>(attn, Wo, bo, x, x2,
                                           total, D_, D_);
    // 5. LN2
    ln_kernel<<<total, 256>>>(x2, g2, beta2, xn);
    // 6. FC1 + GELU
    gemm_k<2><<<dim3(DFF_ / 128, mb), 256>>>(xn, W1, b_fc1, nullptr, mid,
                                             total, DFF_, D_);
    // 7. FC2 + residual -> out
    gemm_k<1><<<dim3(D_ / 128, mb), 256>>>(mid, W2, b_fc2, x2, out,
                                           total, D_, DFF_);
}

// round 4
// speedup vs baseline: 1.9925x; 1.9925x over previous
#include <cuda_runtime.h>
#include <math.h>
#include <stdint.h>

#define D_    768
#define H_    12
#define HD_   64
#define DFF_  3072
#define MAXT  8192
#define SMAX_ 1024

// ---------------- scratch (no allocations allowed) ----------------
__device__ float g_xn  [(size_t)MAXT * D_];
__device__ float g_qkv [(size_t)MAXT * 3 * D_];
__device__ float g_attn[(size_t)MAXT * D_];
__device__ float g_x2  [(size_t)MAXT * D_];
__device__ float g_mid [(size_t)MAXT * DFF_];
__device__ float g_WqkvT[(size_t)3 * D_ * D_];
__device__ float g_WoT  [(size_t)D_ * D_];
__device__ float g_W1T  [(size_t)DFF_ * D_];
__device__ float g_W2T  [(size_t)D_ * DFF_];

// ---------------- helpers ----------------
__device__ __forceinline__ uint32_t smem_u32(const void* p) {
    uint32_t a;
    asm("{ .reg .u64 t; cvta.to.shared.u64 t, %1; cvt.u32.u64 %0, t; }" : "=r"(a) : "l"(p));
    return a;
}
__device__ __forceinline__ float rna_tf32(float x) {
    uint32_t u;
    asm("cvt.rna.tf32.f32 %0, %1;" : "=r"(u) : "f"(x));
    return __uint_as_float(u);
}
#define CP_ASYNC16(dst, src) \
    asm volatile("cp.async.cg.shared.global [%0], [%1], 16;" :: "r"(dst), "l"(src) : "memory")
#define CP_COMMIT() asm volatile("cp.async.commit_group;" ::: "memory")
#define CP_WAIT(n)  asm volatile("cp.async.wait_group %0;" :: "n"(n) : "memory")

__device__ __forceinline__ void mma_tf32(float* c, const uint32_t* a, const uint32_t* b) {
    asm volatile(
        "mma.sync.aligned.m16n8k8.row.col.f32.tf32.tf32.f32 "
        "{%0,%1,%2,%3}, {%4,%5,%6,%7}, {%8,%9}, {%0,%1,%2,%3};"
        : "+f"(c[0]), "+f"(c[1]), "+f"(c[2]), "+f"(c[3])
        : "r"(a[0]), "r"(a[1]), "r"(a[2]), "r"(a[3]), "r"(b[0]), "r"(b[1]));
}

// ---------------- transpose + tf32 round: WT[n][k] = rna(W[k][n]) ----------------
__global__ void __launch_bounds__(256) transpose_rna(const float* __restrict__ W,
                                                     float* __restrict__ WT,
                                                     int K, int N) {
    __shared__ float tile[32][33];
    int tx = threadIdx.x, ty = threadIdx.y;
    int n0 = blockIdx.x * 32, k0 = blockIdx.y * 32;
#pragma unroll
    for (int i = 0; i < 4; i++)
        tile[ty + 8 * i][tx] = W[(size_t)(k0 + ty + 8 * i) * N + n0 + tx];
    __syncthreads();
#pragma unroll
    for (int i = 0; i < 4; i++)
        WT[(size_t)(n0 + ty + 8 * i) * K + k0 + tx] = rna_tf32(tile[tx][ty + 8 * i]);
}

// ---------------- LayerNorm (tf32-rounded output) ----------------
__global__ void __launch_bounds__(256) ln_kernel(const float* __restrict__ x,
                                                 const float* __restrict__ g,
                                                 const float* __restrict__ be,
                                                 float* __restrict__ y) {
    int t = blockIdx.x;
    const float* xr = x + (size_t)t * D_;
    float*       yr = y + (size_t)t * D_;
    int tid = threadIdx.x;
    float v0 = xr[tid], v1 = xr[tid + 256], v2 = xr[tid + 512];
    float s  = v0 + v1 + v2;
    float s2 = v0 * v0 + v1 * v1 + v2 * v2;
    __shared__ float sh1[256], sh2[256];
    sh1[tid] = s; sh2[tid] = s2;
    __syncthreads();
    for (int o = 128; o > 0; o >>= 1) {
        if (tid < o) { sh1[tid] += sh1[tid + o]; sh2[tid] += sh2[tid + o]; }
        __syncthreads();
    }
    float mu  = sh1[0] * (1.0f / D_);
    float var = sh2[0] * (1.0f / D_) - mu * mu;
    float r   = rsqrtf(var + 1e-6f);
    yr[tid]       = rna_tf32((v0 - mu) * r * g[tid]       + be[tid]);
    yr[tid + 256] = rna_tf32((v1 - mu) * r * g[tid + 256] + be[tid + 256]);
    yr[tid + 512] = rna_tf32((v2 - mu) * r * g[tid + 512] + be[tid + 512]);
}

// ---------------- tf32 mma.sync GEMM: C[M,N] = A[M,K] @ BT[N,K]^T + epi ----------
// CTA 128x128, 128 threads, 4 warps (2x2), warp tile 64x64.
// smem rows padded to 20 floats (80B: cp.async-aligned, conflict-free LDS).
// EPI: 0 = +bias, 1 = +bias+residual, 2 = +bias, GELU, tf32-round
#define TS 20
template <int EPI>
__global__ void __launch_bounds__(128) tgemm(const float* __restrict__ A,
                                             const float* __restrict__ BT,
                                             const float* __restrict__ bias,
                                             const float* __restrict__ res,
                                             float* __restrict__ C,
                                             int M, int N, int K) {
    __shared__ float As[2][128 * TS];
    __shared__ float Bs[2][128 * TS];

    int tid = threadIdx.x;
    int lane = tid & 31, wid = tid >> 5;
    int warpM = wid >> 1, warpN = wid & 1;
    int g = lane >> 2, t4 = lane & 3;
    int bm = blockIdx.y * 128, bn = blockIdx.x * 128;

    const float* gA = A  + (size_t)bm * K;
    const float* gB = BT + (size_t)bn * K;

    int lrow = tid >> 2;      // 0..31 (+32i)
    int lc4  = tid & 3;       // float4 index within 16-float row

    float acc[4][8][4];
#pragma unroll
    for (int mf = 0; mf < 4; mf++)
#pragma unroll
        for (int nf = 0; nf < 8; nf++)
#pragma unroll
            for (int r = 0; r < 4; r++) acc[mf][nf][r] = 0.f;

    uint32_t sA0 = smem_u32(&As[0][0]), sB0 = smem_u32(&Bs[0][0]);
    int nc = K >> 4;

    // prologue: load chunk 0 into stage 0
    {
        const float* a0 = gA + lc4 * 4;
        const float* b0 = gB + lc4 * 4;
#pragma unroll
        for (int i = 0; i < 4; i++) {
            int row = lrow + 32 * i;
            uint32_t off = (uint32_t)(row * TS + lc4 * 4) * 4;
            CP_ASYNC16(sA0 + off, a0 + (size_t)row * K);
            CP_ASYNC16(sB0 + off, b0 + (size_t)row * K);
        }
        CP_COMMIT();
    }

    for (int c = 0; c < nc; c++) {
        int st = c & 1;
        if (c + 1 < nc) {
            int k0 = (c + 1) << 4;
            uint32_t sa = sA0 + ((c + 1) & 1) * (128 * TS * 4);
            uint32_t sb = sB0 + ((c + 1) & 1) * (128 * TS * 4);
            const float* a0 = gA + k0 + lc4 * 4;
            const float* b0 = gB + k0 + lc4 * 4;
#pragma unroll
            for (int i = 0; i < 4; i++) {
                int row = lrow + 32 * i;
                uint32_t off = (uint32_t)(row * TS + lc4 * 4) * 4;
                CP_ASYNC16(sa + off, a0 + (size_t)row * K);
                CP_ASYNC16(sb + off, b0 + (size_t)row * K);
            }
            CP_COMMIT();
            CP_WAIT(1);
        } else {
            CP_WAIT(0);
        }
        __syncthreads();

        const float* as = &As[st][0];
        const float* bs = &Bs[st][0];
#pragma unroll
        for (int ko = 0; ko < 16; ko += 8) {
            uint32_t af[4][4];
#pragma unroll
            for (int mf = 0; mf < 4; mf++) {
                int r = warpM * 64 + mf * 16 + g;
                af[mf][0] = __float_as_uint(as[r * TS + ko + t4]);
                af[mf][1] = __float_as_uint(as[(r + 8) * TS + ko + t4]);
                af[mf][2] = __float_as_uint(as[r * TS + ko + t4 + 4]);
                af[mf][3] = __float_as_uint(as[(r + 8) * TS + ko + t4 + 4]);
            }
            uint32_t bf[8][2];
#pragma unroll
            for (int nf = 0; nf < 8; nf++) {
                int n = warpN * 64 + nf * 8 + g;
                bf[nf][0] = __float_as_uint(bs[n * TS + ko + t4]);
                bf[nf][1] = __float_as_uint(bs[n * TS + ko + t4 + 4]);
            }
#pragma unroll
            for (int mf = 0; mf < 4; mf++)
#pragma unroll
                for (int nf = 0; nf < 8; nf++)
                    mma_tf32(acc[mf][nf], af[mf], bf[nf]);
        }
        __syncthreads();
    }

    // epilogue
#pragma unroll
    for (int mf = 0; mf < 4; mf++) {
        int r0 = bm + warpM * 64 + mf * 16 + g;
#pragma unroll
        for (int nf = 0; nf < 8; nf++) {
            int cc = bn + warpN * 64 + nf * 8 + t4 * 2;
            float b0 = bias[cc], b1 = bias[cc + 1];
            float v00 = acc[mf][nf][0] + b0, v01 = acc[mf][nf][1] + b1;
            float v10 = acc[mf][nf][2] + b0, v11 = acc[mf][nf][3] + b1;
            if (EPI == 1) {
                const float* rp0 = res + (size_t)r0 * N + cc;
                const float* rp1 = res + (size_t)(r0 + 8) * N + cc;
                v00 += rp0[0]; v01 += rp0[1];
                v10 += rp1[0]; v11 += rp1[1];
            }
            if (EPI == 2) {
                v00 = rna_tf32(0.5f * v00 * (1.0f + erff(v00 * 0.70710678118654752f)));
                v01 = rna_tf32(0.5f * v01 * (1.0f + erff(v01 * 0.70710678118654752f)));
                v10 = rna_tf32(0.5f * v10 * (1.0f + erff(v10 * 0.70710678118654752f)));
                v11 = rna_tf32(0.5f * v11 * (1.0f + erff(v11 * 0.70710678118654752f)));
            }
            float2 w0 = make_float2(v00, v01);
            float2 w1 = make_float2(v10, v11);
            *(float2*)(C + (size_t)r0 * N + cc)       = w0;
            *(float2*)(C + (size_t)(r0 + 8) * N + cc) = w1;
        }
    }
}

// ---------------- Ragged flash attention (fp32; tf32-rounded output) ------------
__global__ void __launch_bounds__(256) attn_kernel(const float* __restrict__ qkv,
                                                   const int* __restrict__ cu,
                                                   float* __restrict__ out) {
    int qt = blockIdx.x, h = blockIdx.y, b = blockIdx.z;
    int base = cu[b];
    int len  = cu[b + 1] - base;
    int q0   = qt * 32;
    if (q0 >= len) return;
    int nq = min(32, len - q0);

    __shared__ float Qs[32][68];
    __shared__ float KsT[64][68];
    __shared__ float Vs[64][68];
    __shared__ float Ps[32][68];

    int tid = threadIdx.x;
    for (int idx = tid; idx < 32 * 64; idx += 256) {
        int qi = idx >> 6, d = idx & 63;
        Qs[qi][d] = (qi < nq)
            ? qkv[(size_t)(base + q0 + qi) * 2304 + h * 64 + d] * 0.125f
            : 0.f;
    }

    int qg = tid >> 4;
    int kx = tid & 15;
    int qa = qg * 2, qb = qg * 2 + 1;

    float m0 = -1e30f, m1 = -1e30f, l0 = 0.f, l1 = 0.f;
    float o0[4] = {0.f, 0.f, 0.f, 0.f}, o1[4] = {0.f, 0.f, 0.f, 0.f};

    for (int k0 = 0; k0 < len; k0 += 64) {
        int nk = min(64, len - k0);
        __syncthreads();
        for (int idx = tid; idx < 64 * 64; idx += 256) {
            int j = idx >> 6, d = idx & 63;
            float kv = 0.f, vv = 0.f;
            if (j < nk) {
                size_t r = (size_t)(base + k0 + j) * 2304 + h * 64 + d;
                kv = qkv[r + 768];
                vv = qkv[r + 1536];
            }
            KsT[d][j] = kv;
            Vs[j][d]  = vv;
        }
        __syncthreads();

        float s[2][4];
#pragma unroll
        for (int cc = 0; cc < 4; cc++) { s[0][cc] = 0.f; s[1][cc] = 0.f; }
#pragma unroll
        for (int d = 0; d < 64; d++) {
            float qv0 = Qs[qa][d];
            float qv1 = Qs[qb][d];
            float4 kq = *(const float4*)&KsT[d][kx * 4];
            s[0][0] += qv0 * kq.x; s[0][1] += qv0 * kq.y;
            s[0][2] += qv0 * kq.z; s[0][3] += qv0 * kq.w;
            s[1][0] += qv1 * kq.x; s[1][1] += qv1 * kq.y;
            s[1][2] += qv1 * kq.z; s[1][3] += qv1 * kq.w;
        }
#pragma unroll
        for (int cc = 0; cc < 4; cc++) {
            if (kx * 4 + cc >= nk) { s[0][cc] = -1e30f; s[1][cc] = -1e30f; }
        }

        float tm0 = fmaxf(fmaxf(s[0][0], s[0][1]), fmaxf(s[0][2], s[0][3]));
        float tm1 = fmaxf(fmaxf(s[1][0], s[1][1]), fmaxf(s[1][2], s[1][3]));
#pragma unroll
        for (int off = 8; off >= 1; off >>= 1) {
            tm0 = fmaxf(tm0, __shfl_xor_sync(0xffffffffu, tm0, off));
            tm1 = fmaxf(tm1, __shfl_xor_sync(0xffffffffu, tm1, off));
        }
        float nm0 = fmaxf(m0, tm0), nm1 = fmaxf(m1, tm1);
        float sc0 = __expf(m0 - nm0), sc1 = __expf(m1 - nm1);

        float p0[4], p1[4];
        float ls0 = 0.f, ls1 = 0.f;
#pragma unroll
        for (int cc = 0; cc < 4; cc++) {
            p0[cc] = __expf(s[0][cc] - nm0);
            p1[cc] = __expf(s[1][cc] - nm1);
            ls0 += p0[cc]; ls1 += p1[cc];
        }
        *(float4*)&Ps[qa][kx * 4] = *(float4*)p0;
        *(float4*)&Ps[qb][kx * 4] = *(float4*)p1;
#pragma unroll
        for (int off = 8; off >= 1; off >>= 1) {
            ls0 += __shfl_xor_sync(0xffffffffu, ls0, off);
            ls1 += __shfl_xor_sync(0xffffffffu, ls1, off);
        }
        l0 = l0 * sc0 + ls0;
        l1 = l1 * sc1 + ls1;
        m0 = nm0; m1 = nm1;

#pragma unroll
        for (int dd = 0; dd < 4; dd++) { o0[dd] *= sc0; o1[dd] *= sc1; }

        __syncthreads();

#pragma unroll 8
        for (int j = 0; j < 64; j++) {
            float pj0 = Ps[qa][j];
            float pj1 = Ps[qb][j];
            float4 vv = *(const float4*)&Vs[j][kx * 4];
            o0[0] += pj0 * vv.x; o0[1] += pj0 * vv.y;
            o0[2] += pj0 * vv.z; o0[3] += pj0 * vv.w;
            o1[0] += pj1 * vv.x; o1[1] += pj1 * vv.y;
            o1[2] += pj1 * vv.z; o1[3] += pj1 * vv.w;
        }
    }

    float inv0 = 1.0f / l0, inv1 = 1.0f / l1;
    if (qa < nq) {
        float w[4];
#pragma unroll
        for (int dd = 0; dd < 4; dd++) w[dd] = rna_tf32(o0[dd] * inv0);
        *(float4*)&out[(size_t)(base + q0 + qa) * D_ + h * 64 + kx * 4] = *(float4*)w;
    }
    if (qb < nq) {
        float w[4];
#pragma unroll
        for (int dd = 0; dd < 4; dd++) w[dd] = rna_tf32(o1[dd] * inv1);
        *(float4*)&out[(size_t)(base + q0 + qb) * D_ + h * 64 + kx * 4] = *(float4*)w;
    }
}

// ---------------- host launch ----------------
extern "C" void kernel_launch(void* const* d_in, const int* in_sizes, int n_in,
                              void* d_out, int out_size) {
    const float* x     = (const float*)d_in[0];
    const int*   cu    = (const int*)  d_in[1];
    const float* g1    = (const float*)d_in[2];
    const float* beta1 = (const float*)d_in[3];
    const float* Wqkv  = (const float*)d_in[4];
    const float* bqkv  = (const float*)d_in[5];
    const float* Wo    = (const float*)d_in[6];
    const float* bo    = (const float*)d_in[7];
    const float* g2    = (const float*)d_in[8];
    const float* beta2 = (const float*)d_in[9];
    const float* W1    = (const float*)d_in[10];
    const float* b_fc1 = (const float*)d_in[11];
    const float* W2    = (const float*)d_in[12];
    const float* b_fc2 = (const float*)d_in[13];
    float* out = (float*)d_out;

    int total = in_sizes[0] / D_;   // 6144
    int nb    = in_sizes[1] - 1;    // 8

    float *xn, *qkv, *attn, *x2, *mid, *wqkvT, *woT, *w1T, *w2T;
    cudaGetSymbolAddress((void**)&xn,    g_xn);
    cudaGetSymbolAddress((void**)&qkv,   g_qkv);
    cudaGetSymbolAddress((void**)&attn,  g_attn);
    cudaGetSymbolAddress((void**)&x2,    g_x2);
    cudaGetSymbolAddress((void**)&mid,   g_mid);
    cudaGetSymbolAddress((void**)&wqkvT, g_WqkvT);
    cudaGetSymbolAddress((void**)&woT,   g_WoT);
    cudaGetSymbolAddress((void**)&w1T,   g_W1T);
    cudaGetSymbolAddress((void**)&w2T,   g_W2T);

    int mb = total / 128;
    dim3 tb(32, 8);

    // weight transposes + tf32 rounding
    transpose_rna<<<dim3(3 * D_ / 32, D_ / 32), tb>>>(Wqkv, wqkvT, D_, 3 * D_);
    transpose_rna<<<dim3(D_ / 32, D_ / 32),     tb>>>(Wo,   woT,   D_, D_);
    transpose_rna<<<dim3(DFF_ / 32, D_ / 32),   tb>>>(W1,   w1T,   D_, DFF_);
    transpose_rna<<<dim3(D_ / 32, DFF_ / 32),   tb>>>(W2,   w2T,   DFF_, D_);

    // 1. LN1 (tf32-rounded)
    ln_kernel<<<total, 256>>>(x, g1, beta1, xn);
    // 2. QKV projection
    tgemm<0><<<dim3(3 * D_ / 128, mb), 128>>>(xn, wqkvT, bqkv, nullptr,
                                              qkv, total, 3 * D_, D_);
    // 3. ragged attention
    attn_kernel<<<dim3(SMAX_ / 32, H_, nb), 256>>>(qkv, cu, attn);
    // 4. output projection + residual
    tgemm<1><<<dim3(D_ / 128, mb), 128>>>(attn, woT, bo, x, x2, total, D_, D_);
    // 5. LN2 (tf32-rounded)
    ln_kernel<<<total, 256>>>(x2, g2, beta2, xn);
    // 6. FC1 + GELU (tf32-rounded)
    tgemm<2><<<dim3(DFF_ / 128, mb), 128>>>(xn, w1T, b_fc1, nullptr,
                                            mid, total, DFF_, D_);
    // 7. FC2 + residual -> out
    tgemm<1><<<dim3(D_ / 128, mb), 128>>>(mid, w2T, b_fc2, x2,
                                          out, total, D_, DFF_);
}